// round 12
// baseline (speedup 1.0000x reference)
#include <cuda_runtime.h>
#include <math.h>

#define NB 32
#define CCH 384
#define HWP 3136
#define MM 8
#define DD 768
#define EE 768   // 2*C

// ---------------- device scratch (no allocations allowed) ----------------
__device__ __align__(16) float g_Kt[NB * CCH * MM]; // [n][c][k]
__device__ __align__(16) float g_Vt[NB * CCH * MM]; // [n][c][k]

// ---------------- kernel 1: kv = clip(gf @ W^T + b, 0, 6) -> g_Kt / g_Vt ----
#define KV_EB 48
#define KV_RB 16
#define KV_KC 96

__device__ __forceinline__ void kv_store(int row, int e, float v) {
    int n = row >> 3;
    int m = row & 7;
    if (e < CCH) g_Kt[((size_t)n * CCH + e) * MM + m] = v;
    else         g_Vt[((size_t)n * CCH + (e - CCH)) * MM + m] = v;
}

__global__ __launch_bounds__(192) void k_kv(const float* __restrict__ gf,
                                            const float* __restrict__ W,
                                            const float* __restrict__ bias) {
    __shared__ float Wc[KV_KC][KV_EB + 2];
    __shared__ float Gc[KV_RB][KV_KC];
    int t   = threadIdx.x;
    int eb0 = blockIdx.x * KV_EB;
    int rb0 = blockIdx.y * KV_RB;
    int ri  = t / 24;   // 0..7  -> row pair
    int ei  = t % 24;   // 0..23 -> e pair

    float a00 = 0.f, a01 = 0.f, a10 = 0.f, a11 = 0.f;

    for (int kc = 0; kc < DD; kc += KV_KC) {
        __syncthreads();
#pragma unroll
        for (int q = 0; q < 6; q++) {
            int idx = t + q * 192;            // 0..1151 = 48 rows * 24 f4
            int ee = idx / 24, dq = idx % 24;
            float4 v = *(const float4*)(W + (size_t)(eb0 + ee) * DD + kc + dq * 4);
            Wc[dq * 4 + 0][ee] = v.x;
            Wc[dq * 4 + 1][ee] = v.y;
            Wc[dq * 4 + 2][ee] = v.z;
            Wc[dq * 4 + 3][ee] = v.w;
        }
#pragma unroll
        for (int q = 0; q < 2; q++) {
            int idx = t + q * 192;            // 0..383 = 16*24
            int rr = idx / 24, jj = idx % 24;
            float4 v = *(const float4*)(gf + (size_t)(rb0 + rr) * DD + kc + jj * 4);
            *(float4*)(&Gc[rr][jj * 4]) = v;
        }
        __syncthreads();
#pragma unroll 8
        for (int dd = 0; dd < KV_KC; dd++) {
            float2 w2 = *(const float2*)(&Wc[dd][ei * 2]);
            float g0 = Gc[2 * ri][dd];
            float g1 = Gc[2 * ri + 1][dd];
            a00 += g0 * w2.x; a01 += g0 * w2.y;
            a10 += g1 * w2.x; a11 += g1 * w2.y;
        }
    }

    int e0 = eb0 + 2 * ei;
    float b0 = bias[e0], b1 = bias[e0 + 1];
    float v00 = fminf(fmaxf(a00 + b0, 0.f), 6.f);
    float v01 = fminf(fmaxf(a01 + b1, 0.f), 6.f);
    float v10 = fminf(fmaxf(a10 + b0, 0.f), 6.f);
    float v11 = fminf(fmaxf(a11 + b1, 0.f), 6.f);
    int r0 = rb0 + 2 * ri;
    kv_store(r0,     e0,     v00);
    kv_store(r0,     e0 + 1, v01);
    kv_store(r0 + 1, e0,     v10);
    kv_store(r0 + 1, e0 + 1, v11);
}

// ---------------- kernel 2: fused attention + residual ----------------
// v3: 2 pixels per thread (float2), NO register-resident x (residual re-read
// hits L2), 128-thread CTAs, 8 CTAs/SM.
// Lane map: part r = lane>>3 (96 ch), pixel pair = lane&7; warp = 16 px,
// CTA = 4 warps = 64 px. Grid (49, 32) exact.
// K/V smem skew: f4 index(c, half) = 2c + 2*(c/96) + half ; part base = r*194
// -> the 4 parts' broadcast LDS.128 land on disjoint bank groups.
__global__ __launch_bounds__(128, 8) void k_attn(const float* __restrict__ x,
                                                 float* __restrict__ out) {
    __shared__ float4 Ks4[774];
    __shared__ float4 Vs4[774];

    int tid  = threadIdx.x;
    int n    = blockIdx.y;
    int lane = tid & 31;
    int warp = tid >> 5;
    int r    = lane >> 3;                        // 0..3
    int p    = blockIdx.x * 64 + warp * 16 + (lane & 7) * 2;

    const float4* Kt4 = (const float4*)g_Kt + (size_t)n * (CCH * MM / 4);
    const float4* Vt4 = (const float4*)g_Vt + (size_t)n * (CCH * MM / 4);
#pragma unroll
    for (int i = tid; i < 768; i += 128) {
        int c = i >> 1, half = i & 1;
        int dst = 2 * c + 2 * (c / 96) + half;
        Ks4[dst] = Kt4[i];
        Vs4[dst] = Vt4[i];
    }
    __syncthreads();

    const float* xp = x + ((size_t)n * CCH + r * 96) * HWP + p;
    int base = r * 194;

    // ---- pass 1: partial scores for both pixels over 96 channels ----
    float sA0=0.f,sA1=0.f,sA2=0.f,sA3=0.f,sA4=0.f,sA5=0.f,sA6=0.f,sA7=0.f;
    float sB0=0.f,sB1=0.f,sB2=0.f,sB3=0.f,sB4=0.f,sB5=0.f,sB6=0.f,sB7=0.f;
#pragma unroll 8
    for (int j = 0; j < 96; j++) {
        float2 xv = *(const float2*)(xp + (size_t)j * HWP);
        float4 ka = Ks4[base + 2 * j];
        float4 kb = Ks4[base + 2 * j + 1];
        sA0 += xv.x * ka.x; sA1 += xv.x * ka.y; sA2 += xv.x * ka.z; sA3 += xv.x * ka.w;
        sA4 += xv.x * kb.x; sA5 += xv.x * kb.y; sA6 += xv.x * kb.z; sA7 += xv.x * kb.w;
        sB0 += xv.y * ka.x; sB1 += xv.y * ka.y; sB2 += xv.y * ka.z; sB3 += xv.y * ka.w;
        sB4 += xv.y * kb.x; sB5 += xv.y * kb.y; sB6 += xv.y * kb.z; sB7 += xv.y * kb.w;
    }

    // ---- reduce across the 4 parts (lanes l, l^8, l^16, l^24) ----
#define RED4(v) v += __shfl_xor_sync(0xffffffffu, v, 8); \
                v += __shfl_xor_sync(0xffffffffu, v, 16);
    RED4(sA0) RED4(sA1) RED4(sA2) RED4(sA3)
    RED4(sA4) RED4(sA5) RED4(sA6) RED4(sA7)
    RED4(sB0) RED4(sB1) RED4(sB2) RED4(sB3)
    RED4(sB4) RED4(sB5) RED4(sB6) RED4(sB7)
#undef RED4

    // ---- softmax over 8 heads, per pixel (all lanes redundantly) ----
    float mxA = fmaxf(fmaxf(fmaxf(sA0, sA1), fmaxf(sA2, sA3)),
                      fmaxf(fmaxf(sA4, sA5), fmaxf(sA6, sA7)));
    float a0 = __expf(sA0 - mxA), a1 = __expf(sA1 - mxA);
    float a2 = __expf(sA2 - mxA), a3 = __expf(sA3 - mxA);
    float a4 = __expf(sA4 - mxA), a5 = __expf(sA5 - mxA);
    float a6 = __expf(sA6 - mxA), a7 = __expf(sA7 - mxA);
    float invA = __fdividef(1.f, a0+a1+a2+a3+a4+a5+a6+a7);
    a0*=invA; a1*=invA; a2*=invA; a3*=invA; a4*=invA; a5*=invA; a6*=invA; a7*=invA;

    float mxB = fmaxf(fmaxf(fmaxf(sB0, sB1), fmaxf(sB2, sB3)),
                      fmaxf(fmaxf(sB4, sB5), fmaxf(sB6, sB7)));
    float b0 = __expf(sB0 - mxB), b1 = __expf(sB1 - mxB);
    float b2 = __expf(sB2 - mxB), b3 = __expf(sB3 - mxB);
    float b4 = __expf(sB4 - mxB), b5 = __expf(sB5 - mxB);
    float b6 = __expf(sB6 - mxB), b7 = __expf(sB7 - mxB);
    float invB = __fdividef(1.f, b0+b1+b2+b3+b4+b5+b6+b7);
    b0*=invB; b1*=invB; b2*=invB; b3*=invB; b4*=invB; b5*=invB; b6*=invB; b7*=invB;

    // ---- pass 2: out = attn.V + x (x re-read; hits L2, loaded ~us ago) ----
    float* op = out + ((size_t)n * CCH + r * 96) * HWP + p;
#pragma unroll 8
    for (int j = 0; j < 96; j++) {
        float4 va = Vs4[base + 2 * j];
        float4 vb = Vs4[base + 2 * j + 1];
        float accA = a0 * va.x + a1 * va.y + a2 * va.z + a3 * va.w
                   + a4 * vb.x + a5 * vb.y + a6 * vb.z + a7 * vb.w;
        float accB = b0 * va.x + b1 * va.y + b2 * va.z + b3 * va.w
                   + b4 * vb.x + b5 * vb.y + b6 * vb.z + b7 * vb.w;
        float2 xv = __ldcs((const float2*)(xp + (size_t)j * HWP));
        float2 o;
        o.x = accA + xv.x;
        o.y = accB + xv.y;
        __stcs((float2*)(op + (size_t)j * HWP), o);
    }
}

// ---------------- launch ----------------
extern "C" void kernel_launch(void* const* d_in, const int* in_sizes, int n_in,
                              void* d_out, int out_size) {
    const float* x  = (const float*)d_in[0];
    const float* gf = (const float*)d_in[1];
    const float* W  = (const float*)d_in[2];
    const float* b  = (const float*)d_in[3];
    float* out = (float*)d_out;

    k_kv<<<dim3(EE / KV_EB, 256 / KV_RB), 192>>>(gf, W, b);
    k_attn<<<dim3(HWP / 64, NB), 128>>>(x, out);
}

// round 13
// speedup vs baseline: 1.0081x; 1.0081x over previous
#include <cuda_runtime.h>
#include <math.h>

#define NB 32
#define CCH 384
#define HWP 3136
#define MM 8
#define DD 768
#define EE 768   // 2*C

// ---------------- device scratch (no allocations allowed) ----------------
__device__ __align__(16) float g_Kt[NB * CCH * MM]; // [n][c][k]
__device__ __align__(16) float g_Vt[NB * CCH * MM]; // [n][c][k]

// ---------------- kernel 1: kv = clip(gf @ W^T + b, 0, 6) -> g_Kt / g_Vt ----
#define KV_EB 48
#define KV_RB 16
#define KV_KC 96

__device__ __forceinline__ void kv_store(int row, int e, float v) {
    int n = row >> 3;
    int m = row & 7;
    if (e < CCH) g_Kt[((size_t)n * CCH + e) * MM + m] = v;
    else         g_Vt[((size_t)n * CCH + (e - CCH)) * MM + m] = v;
}

__global__ __launch_bounds__(192) void k_kv(const float* __restrict__ gf,
                                            const float* __restrict__ W,
                                            const float* __restrict__ bias) {
    __shared__ float Wc[KV_KC][KV_EB + 2];
    __shared__ float Gc[KV_RB][KV_KC];
    int t   = threadIdx.x;
    int eb0 = blockIdx.x * KV_EB;
    int rb0 = blockIdx.y * KV_RB;
    int ri  = t / 24;   // 0..7  -> row pair
    int ei  = t % 24;   // 0..23 -> e pair

    float a00 = 0.f, a01 = 0.f, a10 = 0.f, a11 = 0.f;

    for (int kc = 0; kc < DD; kc += KV_KC) {
        __syncthreads();
#pragma unroll
        for (int q = 0; q < 6; q++) {
            int idx = t + q * 192;            // 0..1151 = 48 rows * 24 f4
            int ee = idx / 24, dq = idx % 24;
            float4 v = *(const float4*)(W + (size_t)(eb0 + ee) * DD + kc + dq * 4);
            Wc[dq * 4 + 0][ee] = v.x;
            Wc[dq * 4 + 1][ee] = v.y;
            Wc[dq * 4 + 2][ee] = v.z;
            Wc[dq * 4 + 3][ee] = v.w;
        }
#pragma unroll
        for (int q = 0; q < 2; q++) {
            int idx = t + q * 192;            // 0..383 = 16*24
            int rr = idx / 24, jj = idx % 24;
            float4 v = *(const float4*)(gf + (size_t)(rb0 + rr) * DD + kc + jj * 4);
            *(float4*)(&Gc[rr][jj * 4]) = v;
        }
        __syncthreads();
#pragma unroll 8
        for (int dd = 0; dd < KV_KC; dd++) {
            float2 w2 = *(const float2*)(&Wc[dd][ei * 2]);
            float g0 = Gc[2 * ri][dd];
            float g1 = Gc[2 * ri + 1][dd];
            a00 += g0 * w2.x; a01 += g0 * w2.y;
            a10 += g1 * w2.x; a11 += g1 * w2.y;
        }
    }

    int e0 = eb0 + 2 * ei;
    float b0 = bias[e0], b1 = bias[e0 + 1];
    float v00 = fminf(fmaxf(a00 + b0, 0.f), 6.f);
    float v01 = fminf(fmaxf(a01 + b1, 0.f), 6.f);
    float v10 = fminf(fmaxf(a10 + b0, 0.f), 6.f);
    float v11 = fminf(fmaxf(a11 + b1, 0.f), 6.f);
    int r0 = rb0 + 2 * ri;
    kv_store(r0,     e0,     v00);
    kv_store(r0,     e0 + 1, v01);
    kv_store(r0 + 1, e0,     v10);
    kv_store(r0 + 1, e0 + 1, v11);
}

// ---------------- kernel 2: fused attention + residual ----------------
// v3: 2 pixels per thread (float2), NO register-resident x (residual re-read
// hits L2), 128-thread CTAs, 8 CTAs/SM.
// Lane map: part r = lane>>3 (96 ch), pixel pair = lane&7; warp = 16 px,
// CTA = 4 warps = 64 px. Grid (49, 32) exact.
// K/V smem skew: f4 index(c, half) = 2c + 2*(c/96) + half ; part base = r*194
// -> the 4 parts' broadcast LDS.128 land on disjoint bank groups.
__global__ __launch_bounds__(128, 8) void k_attn(const float* __restrict__ x,
                                                 float* __restrict__ out) {
    __shared__ float4 Ks4[774];
    __shared__ float4 Vs4[774];

    int tid  = threadIdx.x;
    int n    = blockIdx.y;
    int lane = tid & 31;
    int warp = tid >> 5;
    int r    = lane >> 3;                        // 0..3
    int p    = blockIdx.x * 64 + warp * 16 + (lane & 7) * 2;

    const float4* Kt4 = (const float4*)g_Kt + (size_t)n * (CCH * MM / 4);
    const float4* Vt4 = (const float4*)g_Vt + (size_t)n * (CCH * MM / 4);
#pragma unroll
    for (int i = tid; i < 768; i += 128) {
        int c = i >> 1, half = i & 1;
        int dst = 2 * c + 2 * (c / 96) + half;
        Ks4[dst] = Kt4[i];
        Vs4[dst] = Vt4[i];
    }
    __syncthreads();

    const float* xp = x + ((size_t)n * CCH + r * 96) * HWP + p;
    int base = r * 194;

    // ---- pass 1: partial scores for both pixels over 96 channels ----
    float sA0=0.f,sA1=0.f,sA2=0.f,sA3=0.f,sA4=0.f,sA5=0.f,sA6=0.f,sA7=0.f;
    float sB0=0.f,sB1=0.f,sB2=0.f,sB3=0.f,sB4=0.f,sB5=0.f,sB6=0.f,sB7=0.f;
#pragma unroll 8
    for (int j = 0; j < 96; j++) {
        float2 xv = *(const float2*)(xp + (size_t)j * HWP);
        float4 ka = Ks4[base + 2 * j];
        float4 kb = Ks4[base + 2 * j + 1];
        sA0 += xv.x * ka.x; sA1 += xv.x * ka.y; sA2 += xv.x * ka.z; sA3 += xv.x * ka.w;
        sA4 += xv.x * kb.x; sA5 += xv.x * kb.y; sA6 += xv.x * kb.z; sA7 += xv.x * kb.w;
        sB0 += xv.y * ka.x; sB1 += xv.y * ka.y; sB2 += xv.y * ka.z; sB3 += xv.y * ka.w;
        sB4 += xv.y * kb.x; sB5 += xv.y * kb.y; sB6 += xv.y * kb.z; sB7 += xv.y * kb.w;
    }

    // ---- reduce across the 4 parts (lanes l, l^8, l^16, l^24) ----
#define RED4(v) v += __shfl_xor_sync(0xffffffffu, v, 8); \
                v += __shfl_xor_sync(0xffffffffu, v, 16);
    RED4(sA0) RED4(sA1) RED4(sA2) RED4(sA3)
    RED4(sA4) RED4(sA5) RED4(sA6) RED4(sA7)
    RED4(sB0) RED4(sB1) RED4(sB2) RED4(sB3)
    RED4(sB4) RED4(sB5) RED4(sB6) RED4(sB7)
#undef RED4

    // ---- softmax over 8 heads, per pixel (all lanes redundantly) ----
    float mxA = fmaxf(fmaxf(fmaxf(sA0, sA1), fmaxf(sA2, sA3)),
                      fmaxf(fmaxf(sA4, sA5), fmaxf(sA6, sA7)));
    float a0 = __expf(sA0 - mxA), a1 = __expf(sA1 - mxA);
    float a2 = __expf(sA2 - mxA), a3 = __expf(sA3 - mxA);
    float a4 = __expf(sA4 - mxA), a5 = __expf(sA5 - mxA);
    float a6 = __expf(sA6 - mxA), a7 = __expf(sA7 - mxA);
    float invA = __fdividef(1.f, a0+a1+a2+a3+a4+a5+a6+a7);
    a0*=invA; a1*=invA; a2*=invA; a3*=invA; a4*=invA; a5*=invA; a6*=invA; a7*=invA;

    float mxB = fmaxf(fmaxf(fmaxf(sB0, sB1), fmaxf(sB2, sB3)),
                      fmaxf(fmaxf(sB4, sB5), fmaxf(sB6, sB7)));
    float b0 = __expf(sB0 - mxB), b1 = __expf(sB1 - mxB);
    float b2 = __expf(sB2 - mxB), b3 = __expf(sB3 - mxB);
    float b4 = __expf(sB4 - mxB), b5 = __expf(sB5 - mxB);
    float b6 = __expf(sB6 - mxB), b7 = __expf(sB7 - mxB);
    float invB = __fdividef(1.f, b0+b1+b2+b3+b4+b5+b6+b7);
    b0*=invB; b1*=invB; b2*=invB; b3*=invB; b4*=invB; b5*=invB; b6*=invB; b7*=invB;

    // ---- pass 2: out = attn.V + x (x re-read; hits L2, loaded ~us ago) ----
    float* op = out + ((size_t)n * CCH + r * 96) * HWP + p;
#pragma unroll 8
    for (int j = 0; j < 96; j++) {
        float4 va = Vs4[base + 2 * j];
        float4 vb = Vs4[base + 2 * j + 1];
        float accA = a0 * va.x + a1 * va.y + a2 * va.z + a3 * va.w
                   + a4 * vb.x + a5 * vb.y + a6 * vb.z + a7 * vb.w;
        float accB = b0 * va.x + b1 * va.y + b2 * va.z + b3 * va.w
                   + b4 * vb.x + b5 * vb.y + b6 * vb.z + b7 * vb.w;
        float2 xv = __ldcs((const float2*)(xp + (size_t)j * HWP));
        float2 o;
        o.x = accA + xv.x;
        o.y = accB + xv.y;
        __stcs((float2*)(op + (size_t)j * HWP), o);
    }
}

// ---------------- launch ----------------
extern "C" void kernel_launch(void* const* d_in, const int* in_sizes, int n_in,
                              void* d_out, int out_size) {
    const float* x  = (const float*)d_in[0];
    const float* gf = (const float*)d_in[1];
    const float* W  = (const float*)d_in[2];
    const float* b  = (const float*)d_in[3];
    float* out = (float*)d_out;

    k_kv<<<dim3(EE / KV_EB, 256 / KV_RB), 192>>>(gf, W, b);
    k_attn<<<dim3(HWP / 64, NB), 128>>>(x, out);
}

// round 14
// speedup vs baseline: 1.4676x; 1.4558x over previous
#include <cuda_runtime.h>
#include <math.h>

#define NB 32
#define CCH 384
#define HWP 3136
#define MM 8
#define DD 768
#define EE 768   // 2*C

// ---------------- device scratch (no allocations allowed) ----------------
__device__ __align__(16) float g_Kt[NB * CCH * MM]; // [n][c][k]
__device__ __align__(16) float g_Vt[NB * CCH * MM]; // [n][c][k]

// ---------------- kernel 1: kv = clip(gf @ W^T + b, 0, 6) ----------------
// NT GEMM, no transpose: out[r][e] = dot(gf[r,:], W[e,:]) — both K-major.
// CTA tile: 16 rows x 64 e, d-chunks of 64. 128 threads, 8 outputs each
// (2 rows x 4 e strided by 16). Packed f32x2 FMA halves the FMA floor.
// smem stride 68: 16-lane LDS.128 of W rows = exactly 2 phases (optimal).
#define KB_E 64
#define KB_R 16
#define KB_D 64

__device__ __forceinline__ void fma2(unsigned long long& acc,
                                     unsigned long long a,
                                     unsigned long long b) {
    asm("fma.rn.f32x2 %0, %1, %2, %0;" : "+l"(acc) : "l"(a), "l"(b));
}
__device__ __forceinline__ float hadd2(unsigned long long v) {
    return __uint_as_float((unsigned)(v & 0xffffffffull)) +
           __uint_as_float((unsigned)(v >> 32));
}

__device__ __forceinline__ void kv_store(int row, int e, float v) {
    int n = row >> 3;
    int m = row & 7;
    if (e < CCH) g_Kt[((size_t)n * CCH + e) * MM + m] = v;
    else         g_Vt[((size_t)n * CCH + (e - CCH)) * MM + m] = v;
}

__global__ __launch_bounds__(128) void k_kv(const float* __restrict__ gf,
                                            const float* __restrict__ W,
                                            const float* __restrict__ bias) {
    __shared__ float Wc[KB_E][68];   // 17408 B
    __shared__ float Gc[KB_R][68];   //  4352 B

    int t    = threadIdx.x;
    int lane = t & 31;
    int warp = t >> 5;
    int eb0  = blockIdx.x * KB_E;
    int rb0  = blockIdx.y * KB_R;
    int ei   = lane & 15;            // e = eb0 + ei + 16q
    int rg   = lane >> 4;            // 0..1
    int r0   = warp * 4 + rg * 2;    // local row base (2 rows)

    unsigned long long acc[4][2];
#pragma unroll
    for (int q = 0; q < 4; q++) { acc[q][0] = 0ull; acc[q][1] = 0ull; }

    for (int kc = 0; kc < DD; kc += KB_D) {
        __syncthreads();
        // stage W chunk: 64 rows x 16 f4, coalesced, no transpose
#pragma unroll
        for (int q = 0; q < 8; q++) {
            int idx = t + q * 128;
            int row = idx >> 4, f4 = idx & 15;
            float4 v = *(const float4*)(W + (size_t)(eb0 + row) * DD + kc + f4 * 4);
            *(float4*)(&Wc[row][f4 * 4]) = v;
        }
        // stage gf chunk: 16 rows x 16 f4
#pragma unroll
        for (int q = 0; q < 2; q++) {
            int idx = t + q * 128;
            int row = idx >> 4, f4 = idx & 15;
            float4 v = *(const float4*)(gf + (size_t)(rb0 + row) * DD + kc + f4 * 4);
            *(float4*)(&Gc[row][f4 * 4]) = v;
        }
        __syncthreads();
#pragma unroll
        for (int s = 0; s < 16; s++) {
            ulonglong2 g0 = *(const ulonglong2*)(&Gc[r0][s * 4]);
            ulonglong2 g1 = *(const ulonglong2*)(&Gc[r0 + 1][s * 4]);
#pragma unroll
            for (int q = 0; q < 4; q++) {
                ulonglong2 w = *(const ulonglong2*)(&Wc[ei + 16 * q][s * 4]);
                fma2(acc[q][0], g0.x, w.x);
                fma2(acc[q][0], g0.y, w.y);
                fma2(acc[q][1], g1.x, w.x);
                fma2(acc[q][1], g1.y, w.y);
            }
        }
    }

#pragma unroll
    for (int q = 0; q < 4; q++) {
        int e = eb0 + ei + 16 * q;
        float bv = bias[e];
        float v0 = fminf(fmaxf(hadd2(acc[q][0]) + bv, 0.f), 6.f);
        float v1 = fminf(fmaxf(hadd2(acc[q][1]) + bv, 0.f), 6.f);
        kv_store(rb0 + r0,     e, v0);
        kv_store(rb0 + r0 + 1, e, v1);
    }
}

// ---------------- kernel 2: fused attention + residual (R11, measured 82us) -
// Lane map: part r = lane>>3 (96 ch), pixel = blk*64 + warp*8 + (lane&7)
// -> every x LDG / out STG covers full 32B sectors. 256 threads, 2 CTAs/SM.
// K/V smem skew: f4 index(c, half) = 2c + 2*(c/96) + half ; part base = r*194.
__global__ __launch_bounds__(256, 2) void k_attn(const float* __restrict__ x,
                                                 float* __restrict__ out) {
    __shared__ float4 Ks4[774];
    __shared__ float4 Vs4[774];

    int tid  = threadIdx.x;
    int n    = blockIdx.y;
    int lane = tid & 31;
    int warp = tid >> 5;
    int r    = lane >> 3;                       // 0..3
    int p    = blockIdx.x * 64 + warp * 8 + (lane & 7);

    const float4* Kt4 = (const float4*)g_Kt + (size_t)n * (CCH * MM / 4);
    const float4* Vt4 = (const float4*)g_Vt + (size_t)n * (CCH * MM / 4);
#pragma unroll
    for (int i = tid; i < 768; i += 256) {
        int c = i >> 1, half = i & 1;
        int dst = 2 * c + 2 * (c / 96) + half;
        Ks4[dst] = Kt4[i];
        Vs4[dst] = Vt4[i];
    }
    __syncthreads();

    // ---- pass 1: load x chunk-wise and fold into partial scores ----
    float xr[96];
    float s0=0.f,s1=0.f,s2=0.f,s3=0.f,s4=0.f,s5=0.f,s6=0.f,s7=0.f;
    const float* xp = x + ((size_t)n * CCH + r * 96) * HWP + p;
    int base = r * 194;
#pragma unroll
    for (int ch = 0; ch < 6; ch++) {
#pragma unroll
        for (int u = 0; u < 16; u++)
            xr[ch * 16 + u] = __ldcs(xp + (size_t)(ch * 16 + u) * HWP);
        asm volatile("" ::: "memory");
#pragma unroll
        for (int u = 0; u < 16; u++) {
            int j = ch * 16 + u;
            float xv = xr[j];
            float4 ka = Ks4[base + 2 * j];
            float4 kb = Ks4[base + 2 * j + 1];
            s0 += xv * ka.x; s1 += xv * ka.y; s2 += xv * ka.z; s3 += xv * ka.w;
            s4 += xv * kb.x; s5 += xv * kb.y; s6 += xv * kb.z; s7 += xv * kb.w;
        }
    }

    // ---- reduce across the 4 parts (lanes l, l^8, l^16, l^24) ----
#define RED4(v) v += __shfl_xor_sync(0xffffffffu, v, 8); \
                v += __shfl_xor_sync(0xffffffffu, v, 16);
    RED4(s0) RED4(s1) RED4(s2) RED4(s3)
    RED4(s4) RED4(s5) RED4(s6) RED4(s7)
#undef RED4

    // ---- softmax over 8 heads (every lane computes it redundantly) ----
    float mx = fmaxf(fmaxf(fmaxf(s0, s1), fmaxf(s2, s3)),
                     fmaxf(fmaxf(s4, s5), fmaxf(s6, s7)));
    float e0 = __expf(s0 - mx), e1 = __expf(s1 - mx);
    float e2 = __expf(s2 - mx), e3 = __expf(s3 - mx);
    float e4 = __expf(s4 - mx), e5 = __expf(s5 - mx);
    float e6 = __expf(s6 - mx), e7 = __expf(s7 - mx);
    float inv = __fdividef(1.f, e0+e1+e2+e3+e4+e5+e6+e7);
    float a0 = e0*inv, a1 = e1*inv, a2 = e2*inv, a3 = e3*inv;
    float a4 = e4*inv, a5 = e5*inv, a6 = e6*inv, a7 = e7*inv;

    // ---- pass 2: out[c][p] = attn . V[c][:] + x[c][p]  (x from registers) ----
    float* op = out + ((size_t)n * CCH + r * 96) * HWP + p;
#pragma unroll
    for (int j = 0; j < 96; j++) {
        float4 va = Vs4[base + 2 * j];
        float4 vb = Vs4[base + 2 * j + 1];
        float acc = a0 * va.x + a1 * va.y + a2 * va.z + a3 * va.w
                  + a4 * vb.x + a5 * vb.y + a6 * vb.z + a7 * vb.w;
        __stcs(op + (size_t)j * HWP, acc + xr[j]);
    }
}

// ---------------- launch ----------------
extern "C" void kernel_launch(void* const* d_in, const int* in_sizes, int n_in,
                              void* d_out, int out_size) {
    const float* x  = (const float*)d_in[0];
    const float* gf = (const float*)d_in[1];
    const float* W  = (const float*)d_in[2];
    const float* b  = (const float*)d_in[3];
    float* out = (float*)d_out;

    k_kv<<<dim3(EE / KB_E, 256 / KB_R), 128>>>(gf, W, b);
    k_attn<<<dim3(HWP / 64, NB), 256>>>(x, out);
}

// round 15
// speedup vs baseline: 1.6878x; 1.1500x over previous
#include <cuda_runtime.h>
#include <math.h>

#define NB 32
#define CCH 384
#define HWP 3136
#define MM 8
#define DD 768
#define EE 768   // 2*C

// ---------------- device scratch (no allocations allowed) ----------------
__device__ __align__(16) float g_Kt[NB * CCH * MM]; // [n][c][k]
__device__ __align__(16) float g_Vt[NB * CCH * MM]; // [n][c][k]

// ---------------- kernel 1: kv = clip(gf @ W^T + b, 0, 6) ----------------
// NT GEMM (no transpose), packed f32x2 FMA, software-pipelined chunk loads:
// chunk k+1 is fetched into registers while chunk k is computed from smem.
#define KB_E 64
#define KB_R 16
#define KB_D 64

__device__ __forceinline__ void fma2(unsigned long long& acc,
                                     unsigned long long a,
                                     unsigned long long b) {
    asm("fma.rn.f32x2 %0, %1, %2, %0;" : "+l"(acc) : "l"(a), "l"(b));
}
__device__ __forceinline__ float hadd2(unsigned long long v) {
    return __uint_as_float((unsigned)(v & 0xffffffffull)) +
           __uint_as_float((unsigned)(v >> 32));
}

__device__ __forceinline__ void kv_store(int row, int e, float v) {
    int n = row >> 3;
    int m = row & 7;
    if (e < CCH) g_Kt[((size_t)n * CCH + e) * MM + m] = v;
    else         g_Vt[((size_t)n * CCH + (e - CCH)) * MM + m] = v;
}

__global__ __launch_bounds__(128) void k_kv(const float* __restrict__ gf,
                                            const float* __restrict__ W,
                                            const float* __restrict__ bias) {
    __shared__ float Wc[KB_E][68];   // 17408 B
    __shared__ float Gc[KB_R][68];   //  4352 B

    int t    = threadIdx.x;
    int lane = t & 31;
    int warp = t >> 5;
    int eb0  = blockIdx.x * KB_E;
    int rb0  = blockIdx.y * KB_R;
    int ei   = lane & 15;            // e = eb0 + ei + 16q
    int rg   = lane >> 4;            // 0..1
    int r0   = warp * 4 + rg * 2;    // local row base (2 rows)

    int wrow = t >> 4, wf4 = t & 15; // staging coords (8 rows apart per q)

    unsigned long long acc[4][2];
#pragma unroll
    for (int q = 0; q < 4; q++) { acc[q][0] = 0ull; acc[q][1] = 0ull; }

    // prologue: fetch chunk 0 into registers
    float4 wreg[8], greg[2];
#pragma unroll
    for (int q = 0; q < 8; q++)
        wreg[q] = *(const float4*)(W + (size_t)(eb0 + wrow + q * 8) * DD + wf4 * 4);
#pragma unroll
    for (int q = 0; q < 2; q++)
        greg[q] = *(const float4*)(gf + (size_t)(rb0 + (t >> 4) + q * 8) * DD + wf4 * 4);

    for (int kc = 0; kc < DD; kc += KB_D) {
        __syncthreads();
        // commit staged chunk to smem
#pragma unroll
        for (int q = 0; q < 8; q++)
            *(float4*)(&Wc[wrow + q * 8][wf4 * 4]) = wreg[q];
#pragma unroll
        for (int q = 0; q < 2; q++)
            *(float4*)(&Gc[(t >> 4) + q * 8][wf4 * 4]) = greg[q];
        __syncthreads();
        // prefetch next chunk (latency overlapped with compute below)
        if (kc + KB_D < DD) {
#pragma unroll
            for (int q = 0; q < 8; q++)
                wreg[q] = *(const float4*)(W + (size_t)(eb0 + wrow + q * 8) * DD + kc + KB_D + wf4 * 4);
#pragma unroll
            for (int q = 0; q < 2; q++)
                greg[q] = *(const float4*)(gf + (size_t)(rb0 + (t >> 4) + q * 8) * DD + kc + KB_D + wf4 * 4);
        }
#pragma unroll
        for (int s = 0; s < 16; s++) {
            ulonglong2 g0 = *(const ulonglong2*)(&Gc[r0][s * 4]);
            ulonglong2 g1 = *(const ulonglong2*)(&Gc[r0 + 1][s * 4]);
#pragma unroll
            for (int q = 0; q < 4; q++) {
                ulonglong2 w = *(const ulonglong2*)(&Wc[ei + 16 * q][s * 4]);
                fma2(acc[q][0], g0.x, w.x);
                fma2(acc[q][0], g0.y, w.y);
                fma2(acc[q][1], g1.x, w.x);
                fma2(acc[q][1], g1.y, w.y);
            }
        }
    }

#pragma unroll
    for (int q = 0; q < 4; q++) {
        int e = eb0 + ei + 16 * q;
        float bv = bias[e];
        float v0 = fminf(fmaxf(hadd2(acc[q][0]) + bv, 0.f), 6.f);
        float v1 = fminf(fmaxf(hadd2(acc[q][1]) + bv, 0.f), 6.f);
        kv_store(rb0 + r0,     e, v0);
        kv_store(rb0 + r0 + 1, e, v1);
    }
}

// ---------------- kernel 2: fused attention + residual ----------------
// v4: 2 pixels/thread (float2), 8 parts x 48 channels, xr register prefetch.
// Lane map: part r = lane>>2, pixel pair = lane&3 -> 4 lanes/part cover 32B.
// CTA 128 thr = 4 warps = 32 px. Grid (98, 32).
// K/V smem skew: f4 idx(c, half) = 2c + (c/48) + half ; part base = 97r
// -> 8 parts' broadcast LDS.128 land on the 8 disjoint 4-bank groups.
__global__ __launch_bounds__(128, 3) void k_attn(const float* __restrict__ x,
                                                 float* __restrict__ out) {
    __shared__ float4 Ks4[776];
    __shared__ float4 Vs4[776];

    int tid  = threadIdx.x;
    int n    = blockIdx.y;
    int lane = tid & 31;
    int warp = tid >> 5;
    int r    = lane >> 2;                        // 0..7
    int p    = blockIdx.x * 32 + warp * 8 + (lane & 3) * 2;

    const float4* Kt4 = (const float4*)g_Kt + (size_t)n * (CCH * MM / 4);
    const float4* Vt4 = (const float4*)g_Vt + (size_t)n * (CCH * MM / 4);
#pragma unroll
    for (int i = tid; i < 768; i += 128) {
        int c = i >> 1, half = i & 1;
        int dst = 2 * c + (c / 48) + half;
        Ks4[dst] = Kt4[i];
        Vs4[dst] = Vt4[i];
    }
    __syncthreads();

    const float* xp = x + ((size_t)n * CCH + r * 48) * HWP + p;
    int base = 97 * r;

    // ---- pass 1: chunked x prefetch (kept in regs) + partial scores ----
    float2 xr[48];
    float sA0=0.f,sA1=0.f,sA2=0.f,sA3=0.f,sA4=0.f,sA5=0.f,sA6=0.f,sA7=0.f;
    float sB0=0.f,sB1=0.f,sB2=0.f,sB3=0.f,sB4=0.f,sB5=0.f,sB6=0.f,sB7=0.f;
#pragma unroll
    for (int ch = 0; ch < 3; ch++) {
#pragma unroll
        for (int u = 0; u < 16; u++)
            xr[ch * 16 + u] = __ldcs((const float2*)(xp + (size_t)(ch * 16 + u) * HWP));
        asm volatile("" ::: "memory");
#pragma unroll
        for (int u = 0; u < 16; u++) {
            int j = ch * 16 + u;
            float2 xv = xr[j];
            float4 ka = Ks4[base + 2 * j];
            float4 kb = Ks4[base + 2 * j + 1];
            sA0 += xv.x * ka.x; sA1 += xv.x * ka.y; sA2 += xv.x * ka.z; sA3 += xv.x * ka.w;
            sA4 += xv.x * kb.x; sA5 += xv.x * kb.y; sA6 += xv.x * kb.z; sA7 += xv.x * kb.w;
            sB0 += xv.y * ka.x; sB1 += xv.y * ka.y; sB2 += xv.y * ka.z; sB3 += xv.y * ka.w;
            sB4 += xv.y * kb.x; sB5 += xv.y * kb.y; sB6 += xv.y * kb.z; sB7 += xv.y * kb.w;
        }
    }

    // ---- reduce across the 8 parts (butterfly over lane bits 2..4) ----
#define RED8(v) v += __shfl_xor_sync(0xffffffffu, v, 4);  \
                v += __shfl_xor_sync(0xffffffffu, v, 8);  \
                v += __shfl_xor_sync(0xffffffffu, v, 16);
    RED8(sA0) RED8(sA1) RED8(sA2) RED8(sA3)
    RED8(sA4) RED8(sA5) RED8(sA6) RED8(sA7)
    RED8(sB0) RED8(sB1) RED8(sB2) RED8(sB3)
    RED8(sB4) RED8(sB5) RED8(sB6) RED8(sB7)
#undef RED8

    // ---- softmax over 8 heads, both pixels (all lanes redundantly) ----
    float mxA = fmaxf(fmaxf(fmaxf(sA0, sA1), fmaxf(sA2, sA3)),
                      fmaxf(fmaxf(sA4, sA5), fmaxf(sA6, sA7)));
    float a0 = __expf(sA0 - mxA), a1 = __expf(sA1 - mxA);
    float a2 = __expf(sA2 - mxA), a3 = __expf(sA3 - mxA);
    float a4 = __expf(sA4 - mxA), a5 = __expf(sA5 - mxA);
    float a6 = __expf(sA6 - mxA), a7 = __expf(sA7 - mxA);
    float invA = __fdividef(1.f, a0+a1+a2+a3+a4+a5+a6+a7);
    a0*=invA; a1*=invA; a2*=invA; a3*=invA; a4*=invA; a5*=invA; a6*=invA; a7*=invA;

    float mxB = fmaxf(fmaxf(fmaxf(sB0, sB1), fmaxf(sB2, sB3)),
                      fmaxf(fmaxf(sB4, sB5), fmaxf(sB6, sB7)));
    float b0 = __expf(sB0 - mxB), b1 = __expf(sB1 - mxB);
    float b2 = __expf(sB2 - mxB), b3 = __expf(sB3 - mxB);
    float b4 = __expf(sB4 - mxB), b5 = __expf(sB5 - mxB);
    float b6 = __expf(sB6 - mxB), b7 = __expf(sB7 - mxB);
    float invB = __fdividef(1.f, b0+b1+b2+b3+b4+b5+b6+b7);
    b0*=invB; b1*=invB; b2*=invB; b3*=invB; b4*=invB; b5*=invB; b6*=invB; b7*=invB;

    // ---- pass 2: out = attn.V + x (x from registers) ----
    float* op = out + ((size_t)n * CCH + r * 48) * HWP + p;
#pragma unroll
    for (int j = 0; j < 48; j++) {
        float4 va = Vs4[base + 2 * j];
        float4 vb = Vs4[base + 2 * j + 1];
        float accA = a0 * va.x + a1 * va.y + a2 * va.z + a3 * va.w
                   + a4 * vb.x + a5 * vb.y + a6 * vb.z + a7 * vb.w;
        float accB = b0 * va.x + b1 * va.y + b2 * va.z + b3 * va.w
                   + b4 * vb.x + b5 * vb.y + b6 * vb.z + b7 * vb.w;
        float2 o;
        o.x = accA + xr[j].x;
        o.y = accB + xr[j].y;
        __stcs((float2*)(op + (size_t)j * HWP), o);
    }
}

// ---------------- launch ----------------
extern "C" void kernel_launch(void* const* d_in, const int* in_sizes, int n_in,
                              void* d_out, int out_size) {
    const float* x  = (const float*)d_in[0];
    const float* gf = (const float*)d_in[1];
    const float* W  = (const float*)d_in[2];
    const float* b  = (const float*)d_in[3];
    float* out = (float*)d_out;

    k_kv<<<dim3(EE / KB_E, 256 / KB_R), 128>>>(gf, W, b);
    k_attn<<<dim3(HWP / 32, NB), 128>>>(x, out);
}